// round 1
// baseline (speedup 1.0000x reference)
#include <cuda_runtime.h>
#include <cuda_bf16.h>
#include <math.h>

// Sizes
#define NB   1024      // batch
#define LL   128       // seq length
#define HH   256       // decode hidden
#define II   32        // predictor hidden
#define ZZ   128       // latent

// ---------------- device scratch (no cudaMalloc allowed) ----------------
__device__ float g_t1[NB * 512];
__device__ float g_t2[NB * 512];
__device__ float g_h [NB * HH];
__device__ float g_c [NB * HH];
__device__ float g_x0[NB * HH];
__device__ float g_rW[4 * HH * HH];    // rWih + rWhh  [1024,256]
__device__ float g_rb[4 * HH];
__device__ float g_pb[4 * II];
__device__ float g_outs[(size_t)LL * NB * HH];   // 128*1024*256 floats (134 MB)
__device__ float g_XW  [(size_t)LL * NB * 4 * II]; // 128*1024*128 floats (67 MB)

// ---------------- small helpers ----------------
__device__ __forceinline__ float sigmoidf_(float x) { return 1.0f / (1.0f + expf(-x)); }

// ---------------- prep: fused weight/bias sums ----------------
__global__ void prep_kernel(const float* __restrict__ rWih, const float* __restrict__ rWhh,
                            const float* __restrict__ rbih, const float* __restrict__ rbhh,
                            const float* __restrict__ pbih, const float* __restrict__ pbhh,
                            float* __restrict__ rW, float* __restrict__ rb, float* __restrict__ pb)
{
    int i = blockIdx.x * blockDim.x + threadIdx.x;
    if (i < 4 * HH * HH) rW[i] = rWih[i] + rWhh[i];
    if (i < 4 * HH)      rb[i] = rbih[i] + rbhh[i];
    if (i < 4 * II)      pb[i] = pbih[i] + pbhh[i];
}

// ---------------- generic fused linear: Y = act(X @ W^T + b) ----------------
// X[M,K] row-major, W[N,K] row-major, Y[M,N]. Tiles 64x64, Kt=16, 256 thr, 4x4 micro.
// M,N multiples of 64; K multiple of 16. act: 0=none, 1=leaky(0.2)
__global__ __launch_bounds__(256)
void linear_kernel(const float* __restrict__ X, const float* __restrict__ W,
                   const float* __restrict__ bias, float* __restrict__ Y,
                   int M, int N, int K, int act)
{
    __shared__ float Xs[16][68];
    __shared__ float Ws[16][68];
    const int tid = threadIdx.x;
    const int tm = tid >> 4;          // 0..15
    const int tn = tid & 15;          // 0..15
    const int m0 = blockIdx.x * 64;
    const int n0 = blockIdx.y * 64;

    float acc[4][4];
#pragma unroll
    for (int r = 0; r < 4; ++r)
#pragma unroll
        for (int cidx = 0; cidx < 4; ++cidx) acc[r][cidx] = 0.0f;

    const int lb = tid >> 2;   // 0..63 row within tile
    const int li = tid & 3;    // which 4-float chunk of the 16-k strip

    for (int k0 = 0; k0 < K; k0 += 16) {
        float4 xv = *reinterpret_cast<const float4*>(&X[(size_t)(m0 + lb) * K + k0 + li * 4]);
        Xs[li * 4 + 0][lb] = xv.x; Xs[li * 4 + 1][lb] = xv.y;
        Xs[li * 4 + 2][lb] = xv.z; Xs[li * 4 + 3][lb] = xv.w;
        float4 wv = *reinterpret_cast<const float4*>(&W[(size_t)(n0 + lb) * K + k0 + li * 4]);
        Ws[li * 4 + 0][lb] = wv.x; Ws[li * 4 + 1][lb] = wv.y;
        Ws[li * 4 + 2][lb] = wv.z; Ws[li * 4 + 3][lb] = wv.w;
        __syncthreads();
#pragma unroll
        for (int k = 0; k < 16; ++k) {
            float4 a4 = *reinterpret_cast<const float4*>(&Xs[k][tm * 4]);
            float4 b4 = *reinterpret_cast<const float4*>(&Ws[k][tn * 4]);
            float a[4] = {a4.x, a4.y, a4.z, a4.w};
            float b[4] = {b4.x, b4.y, b4.z, b4.w};
#pragma unroll
            for (int r = 0; r < 4; ++r)
#pragma unroll
                for (int cidx = 0; cidx < 4; ++cidx) acc[r][cidx] += a[r] * b[cidx];
        }
        __syncthreads();
    }

#pragma unroll
    for (int r = 0; r < 4; ++r) {
        int m = m0 + tm * 4 + r;
        float4 o;
        float* po = &o.x;
#pragma unroll
        for (int cidx = 0; cidx < 4; ++cidx) {
            float v = acc[r][cidx] + bias[n0 + tn * 4 + cidx];
            if (act == 1) v = (v >= 0.0f) ? v : 0.2f * v;
            po[cidx] = v;
        }
        *reinterpret_cast<float4*>(&Y[(size_t)m * N + n0 + tn * 4]) = o;
    }
}

// ---------------- fused decode LSTM step ----------------
// gates = A1 @ W1^T (+ A2 @ W2^T) + rb ; c = sig(f)*c + sig(i)*tanh(g); h = sig(o)*tanh(c)
// A*: [1024,256], W*: [1024,256] (gate-row major, order i,f,g,o blocks of 256)
// grid (32, 4): 32-batch x 64-h tiles. 256 threads: tm=warp (8) -> 4 rows each,
// tn=lane -> h indices {tn, 32+tn}, all 4 gates in registers -> fused pointwise.
__global__ __launch_bounds__(256)
void decode_step_kernel(const float* __restrict__ A1, const float* __restrict__ W1,
                        const float* __restrict__ A2, const float* __restrict__ W2,
                        const float* __restrict__ rb,
                        float* __restrict__ Cst, float* __restrict__ Hout)
{
    __shared__ float As[16][36];
    __shared__ float Bs[16][256];
    const int tid = threadIdx.x;
    const int tm = tid >> 5;   // warp 0..7
    const int tn = tid & 31;   // lane
    const int b0 = blockIdx.x * 32;
    const int h0 = blockIdx.y * 64;

    float acc[4][8];
#pragma unroll
    for (int r = 0; r < 4; ++r)
#pragma unroll
        for (int cidx = 0; cidx < 8; ++cidx) acc[r][cidx] = 0.0f;

    // B loader mapping: local col l = q*128 + jj_in_32*4 + g, jj = q*32 + jj_in_32
    const int l = tid;
    const int jj_l = ((l >> 7) << 5) + ((l >> 2) & 31);
    const int g_l = l & 3;
    const int wrow = g_l * 256 + h0 + jj_l;   // row in W [1024,256]

    for (int pass = 0; pass < 2; ++pass) {
        if (pass && A2 == nullptr) break;
        const float* A = pass ? A2 : A1;
        const float* W = pass ? W2 : W1;
        for (int k0 = 0; k0 < 256; k0 += 16) {
            if (tid < 128) {
                int br = tid >> 2, i4 = tid & 3;
                float4 v = *reinterpret_cast<const float4*>(&A[(size_t)(b0 + br) * 256 + k0 + i4 * 4]);
                As[i4 * 4 + 0][br] = v.x; As[i4 * 4 + 1][br] = v.y;
                As[i4 * 4 + 2][br] = v.z; As[i4 * 4 + 3][br] = v.w;
            }
#pragma unroll
            for (int i4 = 0; i4 < 4; ++i4) {
                float4 v = *reinterpret_cast<const float4*>(&W[(size_t)wrow * 256 + k0 + i4 * 4]);
                Bs[i4 * 4 + 0][l] = v.x; Bs[i4 * 4 + 1][l] = v.y;
                Bs[i4 * 4 + 2][l] = v.z; Bs[i4 * 4 + 3][l] = v.w;
            }
            __syncthreads();
#pragma unroll
            for (int k = 0; k < 16; ++k) {
                float4 a4 = *reinterpret_cast<const float4*>(&As[k][tm * 4]);
                float a[4] = {a4.x, a4.y, a4.z, a4.w};
                float4 bl = *reinterpret_cast<const float4*>(&Bs[k][tn * 4]);
                float4 bh = *reinterpret_cast<const float4*>(&Bs[k][128 + tn * 4]);
                float b[8] = {bl.x, bl.y, bl.z, bl.w, bh.x, bh.y, bh.z, bh.w};
#pragma unroll
                for (int r = 0; r < 4; ++r)
#pragma unroll
                    for (int cidx = 0; cidx < 8; ++cidx) acc[r][cidx] += a[r] * b[cidx];
            }
            __syncthreads();
        }
    }

    // fused LSTM pointwise (each thread owns all 4 gates for its (b, h) pairs)
#pragma unroll
    for (int r = 0; r < 4; ++r) {
        int b = b0 + tm * 4 + r;
#pragma unroll
        for (int q = 0; q < 2; ++q) {
            int hidx = h0 + q * 32 + tn;
            float ig = acc[r][q * 4 + 0] + rb[0 * 256 + hidx];
            float fg = acc[r][q * 4 + 1] + rb[1 * 256 + hidx];
            float gg = acc[r][q * 4 + 2] + rb[2 * 256 + hidx];
            float og = acc[r][q * 4 + 3] + rb[3 * 256 + hidx];
            float c_old = Cst[(size_t)b * 256 + hidx];
            float c_new = sigmoidf_(fg) * c_old + sigmoidf_(ig) * tanhf(gg);
            float h_new = sigmoidf_(og) * tanhf(c_new);
            Cst[(size_t)b * 256 + hidx] = c_new;
            Hout[(size_t)b * 256 + hidx] = h_new;
        }
    }
}

// ---------------- predictor LSTM (whole 128-step recurrence) + softmax/sigmoid ----------------
// XW[l,b,:] = outs[l,b] @ pWih^T + (pbih+pbhh) precomputed. Recurrence per batch element:
// 1 warp / element, lane j owns h-index j and gate rows {j, 32+j, 64+j, 96+j}.
__global__ __launch_bounds__(128)
void predictor_kernel(const float* __restrict__ XW, const float* __restrict__ pWhh,
                      float* __restrict__ out)
{
    __shared__ float sWt[32 * 132];   // transposed pWhh: sWt[k*132 + row]
    __shared__ float sh[4][32];
    const int tid = threadIdx.x;
    const int w = tid >> 5;
    const int j = tid & 31;
    const int b = blockIdx.x * 4 + w;

    for (int i = tid; i < 128 * 32; i += 128) {
        int row = i >> 5, k = i & 31;
        sWt[k * 132 + row] = pWhh[i];
    }
    sh[w][j] = 0.0f;
    float cp = 0.0f;
    __syncthreads();

    float nxt[4];
#pragma unroll
    for (int t = 0; t < 4; ++t) nxt[t] = XW[(size_t)b * 128 + t * 32 + j];

    for (int s = 0; s < 128; ++s) {
        float g0 = nxt[0], g1 = nxt[1], g2 = nxt[2], g3 = nxt[3];
        if (s + 1 < 128) {
#pragma unroll
            for (int t = 0; t < 4; ++t)
                nxt[t] = XW[(size_t)((s + 1) * 1024 + b) * 128 + t * 32 + j];
        }
#pragma unroll
        for (int k = 0; k < 32; ++k) {
            float hk = sh[w][k];                 // broadcast
            const float* wr = &sWt[k * 132];
            g0 += hk * wr[j];
            g1 += hk * wr[32 + j];
            g2 += hk * wr[64 + j];
            g3 += hk * wr[96 + j];
        }
        float ig = sigmoidf_(g0);
        float fg = sigmoidf_(g1);
        float gg = tanhf(g2);
        float og = sigmoidf_(g3);
        cp = fg * cp + ig * gg;
        float hv = og * tanhf(cp);
        __syncwarp();
        sh[w][j] = hv;
        __syncwarp();

        // softmax over lanes 0..30, sigmoid on lane 31
        float mv = (j < 31) ? hv : -3.0e38f;
#pragma unroll
        for (int o = 16; o > 0; o >>= 1) mv = fmaxf(mv, __shfl_xor_sync(0xffffffffu, mv, o));
        float e = (j < 31) ? expf(hv - mv) : 0.0f;
        float sum = e;
#pragma unroll
        for (int o = 16; o > 0; o >>= 1) sum += __shfl_xor_sync(0xffffffffu, sum, o);
        float ov = (j < 31) ? (e / sum) : sigmoidf_(hv);
        out[(size_t)(b * 128 + s) * 32 + j] = ov;
    }
}

// ---------------- launch ----------------
extern "C" void kernel_launch(void* const* d_in, const int* in_sizes, int n_in,
                              void* d_out, int out_size)
{
    const float* x    = (const float*)d_in[0];
    const float* W1   = (const float*)d_in[1];
    const float* b1   = (const float*)d_in[2];
    const float* W2   = (const float*)d_in[3];
    const float* b2   = (const float*)d_in[4];
    const float* W3   = (const float*)d_in[5];
    const float* b3   = (const float*)d_in[6];
    const float* Wh1  = (const float*)d_in[7];
    const float* bh1  = (const float*)d_in[8];
    const float* Wh2  = (const float*)d_in[9];
    const float* bh2  = (const float*)d_in[10];
    const float* Wc1  = (const float*)d_in[11];
    const float* bc1  = (const float*)d_in[12];
    const float* Wc2  = (const float*)d_in[13];
    const float* bc2  = (const float*)d_in[14];
    const float* Wx1  = (const float*)d_in[15];
    const float* bx1  = (const float*)d_in[16];
    const float* Wx2  = (const float*)d_in[17];
    const float* bx2  = (const float*)d_in[18];
    const float* rWih = (const float*)d_in[19];
    const float* rWhh = (const float*)d_in[20];
    const float* rbih = (const float*)d_in[21];
    const float* rbhh = (const float*)d_in[22];
    const float* pWih = (const float*)d_in[23];
    const float* pWhh = (const float*)d_in[24];
    const float* pbih = (const float*)d_in[25];
    const float* pbhh = (const float*)d_in[26];

    float *t1, *t2, *hbuf, *cbuf, *x0buf, *rW, *rb, *pb, *outs, *XW;
    cudaGetSymbolAddress((void**)&t1, g_t1);
    cudaGetSymbolAddress((void**)&t2, g_t2);
    cudaGetSymbolAddress((void**)&hbuf, g_h);
    cudaGetSymbolAddress((void**)&cbuf, g_c);
    cudaGetSymbolAddress((void**)&x0buf, g_x0);
    cudaGetSymbolAddress((void**)&rW, g_rW);
    cudaGetSymbolAddress((void**)&rb, g_rb);
    cudaGetSymbolAddress((void**)&pb, g_pb);
    cudaGetSymbolAddress((void**)&outs, g_outs);
    cudaGetSymbolAddress((void**)&XW, g_XW);

    // fused weight/bias sums
    prep_kernel<<<512, 512>>>(rWih, rWhh, rbih, rbhh, pbih, pbhh, rW, rb, pb);

    // MLP trunk + heads (leaky on hidden layers, none on head outputs)
    linear_kernel<<<dim3(16, 8), 256>>>(x,  W1,  b1,  t1, 1024, 512, 128, 1);
    linear_kernel<<<dim3(16, 8), 256>>>(t1, W2,  b2,  t2, 1024, 512, 512, 1);
    linear_kernel<<<dim3(16, 8), 256>>>(t2, W3,  b3,  t1, 1024, 512, 512, 1);   // t1 = t3
    linear_kernel<<<dim3(16, 8), 256>>>(t1, Wh1, bh1, t2, 1024, 512, 512, 1);
    linear_kernel<<<dim3(16, 4), 256>>>(t2, Wh2, bh2, hbuf, 1024, 256, 512, 0);
    linear_kernel<<<dim3(16, 8), 256>>>(t1, Wc1, bc1, t2, 1024, 512, 512, 1);
    linear_kernel<<<dim3(16, 4), 256>>>(t2, Wc2, bc2, cbuf, 1024, 256, 512, 0);
    linear_kernel<<<dim3(16, 8), 256>>>(t1, Wx1, bx1, t2, 1024, 512, 512, 1);
    linear_kernel<<<dim3(16, 4), 256>>>(t2, Wx2, bx2, x0buf, 1024, 256, 512, 0);

    // decode LSTM: step 0 uses (x0, rWih) + (h, rWhh); steps 1.. use fused rW (tok == h)
    decode_step_kernel<<<dim3(32, 4), 256>>>(x0buf, rWih, hbuf, rWhh, rb, cbuf, outs);
    for (int s = 1; s < 128; ++s) {
        decode_step_kernel<<<dim3(32, 4), 256>>>(outs + (size_t)(s - 1) * NB * HH, rW,
                                                 nullptr, nullptr, rb, cbuf,
                                                 outs + (size_t)s * NB * HH);
    }

    // predictor input transform, batched over all steps: XW = outs @ pWih^T + pb
    linear_kernel<<<dim3(2048, 2), 256>>>(outs, pWih, pb, XW, LL * NB, 128, 256, 0);

    // full predictor recurrence + softmax/sigmoid epilogue
    predictor_kernel<<<256, 128>>>(XW, pWhh, (float*)d_out);
}

// round 2
// speedup vs baseline: 1.5151x; 1.5151x over previous
#include <cuda_runtime.h>
#include <cuda_bf16.h>
#include <math.h>

// Sizes
#define NB   1024      // batch
#define LL   128       // seq length
#define HH   256       // decode hidden
#define II   32        // predictor hidden
#define ZZ   128       // latent

// ---------------- device scratch (no cudaMalloc allowed) ----------------
__device__ float g_t1[NB * 512];
__device__ float g_t2[NB * 512];
__device__ float g_h [NB * HH];
__device__ float g_c [NB * HH];
__device__ float g_x0[NB * HH];
__device__ float g_rW[4 * HH * HH];    // rWih + rWhh  [1024,256]
__device__ float g_rb[4 * HH];
__device__ float g_pb[4 * II];
__device__ float g_outs[(size_t)LL * NB * HH];   // 128*1024*256 floats (134 MB)
__device__ float g_XW  [(size_t)LL * NB * 4 * II]; // 128*1024*128 floats (67 MB)

// grid-barrier state (count self-resets; gen monotonically increases; deterministic)
__device__ unsigned g_bar_arrive = 0;
__device__ unsigned g_bar_gen    = 0;

// ---------------- small helpers ----------------
__device__ __forceinline__ float sigmoidf_(float x) { return 1.0f / (1.0f + expf(-x)); }

// packed f32x2 FMA:  d.lo += a.lo*b.lo ; d.hi += a.hi*b.hi
__device__ __forceinline__ void ffma2(unsigned long long& d,
                                      unsigned long long a,
                                      unsigned long long b) {
    asm("fma.rn.f32x2 %0, %1, %2, %0;" : "+l"(d) : "l"(a), "l"(b));
}
// 16B shared load straight into two packed-f32x2 operands
__device__ __forceinline__ void lds_v2u64(unsigned long long& x, unsigned long long& y,
                                          unsigned addr) {
    asm("ld.shared.v2.b64 {%0, %1}, [%2];" : "=l"(x), "=l"(y) : "r"(addr));
}
__device__ __forceinline__ float u64lo(unsigned long long v) {
    return __uint_as_float((unsigned)(v & 0xffffffffull));
}
__device__ __forceinline__ float u64hi(unsigned long long v) {
    return __uint_as_float((unsigned)(v >> 32));
}

// ---------------- prep: fused weight/bias sums ----------------
__global__ void prep_kernel(const float* __restrict__ rWih, const float* __restrict__ rWhh,
                            const float* __restrict__ rbih, const float* __restrict__ rbhh,
                            const float* __restrict__ pbih, const float* __restrict__ pbhh,
                            float* __restrict__ rW, float* __restrict__ rb, float* __restrict__ pb)
{
    int i = blockIdx.x * blockDim.x + threadIdx.x;
    if (i < 4 * HH * HH) rW[i] = rWih[i] + rWhh[i];
    if (i < 4 * HH)      rb[i] = rbih[i] + rbhh[i];
    if (i < 4 * II)      pb[i] = pbih[i] + pbhh[i];
}

// ---------------- generic fused linear: Y = act(X @ W^T + b) ----------------
__global__ __launch_bounds__(256)
void linear_kernel(const float* __restrict__ X, const float* __restrict__ W,
                   const float* __restrict__ bias, float* __restrict__ Y,
                   int M, int N, int K, int act)
{
    __shared__ float Xs[16][68];
    __shared__ float Ws[16][68];
    const int tid = threadIdx.x;
    const int tm = tid >> 4;          // 0..15
    const int tn = tid & 15;          // 0..15
    const int m0 = blockIdx.x * 64;
    const int n0 = blockIdx.y * 64;

    float acc[4][4];
#pragma unroll
    for (int r = 0; r < 4; ++r)
#pragma unroll
        for (int cidx = 0; cidx < 4; ++cidx) acc[r][cidx] = 0.0f;

    const int lb = tid >> 2;   // 0..63 row within tile
    const int li = tid & 3;    // which 4-float chunk of the 16-k strip

    for (int k0 = 0; k0 < K; k0 += 16) {
        float4 xv = *reinterpret_cast<const float4*>(&X[(size_t)(m0 + lb) * K + k0 + li * 4]);
        Xs[li * 4 + 0][lb] = xv.x; Xs[li * 4 + 1][lb] = xv.y;
        Xs[li * 4 + 2][lb] = xv.z; Xs[li * 4 + 3][lb] = xv.w;
        float4 wv = *reinterpret_cast<const float4*>(&W[(size_t)(n0 + lb) * K + k0 + li * 4]);
        Ws[li * 4 + 0][lb] = wv.x; Ws[li * 4 + 1][lb] = wv.y;
        Ws[li * 4 + 2][lb] = wv.z; Ws[li * 4 + 3][lb] = wv.w;
        __syncthreads();
#pragma unroll
        for (int k = 0; k < 16; ++k) {
            float4 a4 = *reinterpret_cast<const float4*>(&Xs[k][tm * 4]);
            float4 b4 = *reinterpret_cast<const float4*>(&Ws[k][tn * 4]);
            float a[4] = {a4.x, a4.y, a4.z, a4.w};
            float b[4] = {b4.x, b4.y, b4.z, b4.w};
#pragma unroll
            for (int r = 0; r < 4; ++r)
#pragma unroll
                for (int cidx = 0; cidx < 4; ++cidx) acc[r][cidx] += a[r] * b[cidx];
        }
        __syncthreads();
    }

#pragma unroll
    for (int r = 0; r < 4; ++r) {
        int m = m0 + tm * 4 + r;
        float4 o;
        float* po = &o.x;
#pragma unroll
        for (int cidx = 0; cidx < 4; ++cidx) {
            float v = acc[r][cidx] + bias[n0 + tn * 4 + cidx];
            if (act == 1) v = (v >= 0.0f) ? v : 0.2f * v;
            po[cidx] = v;
        }
        *reinterpret_cast<float4*>(&Y[(size_t)m * N + n0 + tn * 4]) = o;
    }
}

// ---------------- decode step 0 (two weight matrices; unfused inputs) ----------------
__global__ __launch_bounds__(256)
void decode_step_kernel(const float* __restrict__ A1, const float* __restrict__ W1,
                        const float* __restrict__ A2, const float* __restrict__ W2,
                        const float* __restrict__ rb,
                        float* __restrict__ Cst, float* __restrict__ Hout)
{
    __shared__ float As[16][36];
    __shared__ float Bs[16][256];
    const int tid = threadIdx.x;
    const int tm = tid >> 5;
    const int tn = tid & 31;
    const int b0 = blockIdx.x * 32;
    const int h0 = blockIdx.y * 64;

    float acc[4][8];
#pragma unroll
    for (int r = 0; r < 4; ++r)
#pragma unroll
        for (int cidx = 0; cidx < 8; ++cidx) acc[r][cidx] = 0.0f;

    const int l = tid;
    const int jj_l = ((l >> 7) << 5) + ((l >> 2) & 31);
    const int g_l = l & 3;
    const int wrow = g_l * 256 + h0 + jj_l;

    for (int pass = 0; pass < 2; ++pass) {
        if (pass && A2 == nullptr) break;
        const float* A = pass ? A2 : A1;
        const float* W = pass ? W2 : W1;
        for (int k0 = 0; k0 < 256; k0 += 16) {
            if (tid < 128) {
                int br = tid >> 2, i4 = tid & 3;
                float4 v = *reinterpret_cast<const float4*>(&A[(size_t)(b0 + br) * 256 + k0 + i4 * 4]);
                As[i4 * 4 + 0][br] = v.x; As[i4 * 4 + 1][br] = v.y;
                As[i4 * 4 + 2][br] = v.z; As[i4 * 4 + 3][br] = v.w;
            }
#pragma unroll
            for (int i4 = 0; i4 < 4; ++i4) {
                float4 v = *reinterpret_cast<const float4*>(&W[(size_t)wrow * 256 + k0 + i4 * 4]);
                Bs[i4 * 4 + 0][l] = v.x; Bs[i4 * 4 + 1][l] = v.y;
                Bs[i4 * 4 + 2][l] = v.z; Bs[i4 * 4 + 3][l] = v.w;
            }
            __syncthreads();
#pragma unroll
            for (int k = 0; k < 16; ++k) {
                float4 a4 = *reinterpret_cast<const float4*>(&As[k][tm * 4]);
                float a[4] = {a4.x, a4.y, a4.z, a4.w};
                float4 bl = *reinterpret_cast<const float4*>(&Bs[k][tn * 4]);
                float4 bh = *reinterpret_cast<const float4*>(&Bs[k][128 + tn * 4]);
                float b[8] = {bl.x, bl.y, bl.z, bl.w, bh.x, bh.y, bh.z, bh.w};
#pragma unroll
                for (int r = 0; r < 4; ++r)
#pragma unroll
                    for (int cidx = 0; cidx < 8; ++cidx) acc[r][cidx] += a[r] * b[cidx];
            }
            __syncthreads();
        }
    }

#pragma unroll
    for (int r = 0; r < 4; ++r) {
        int b = b0 + tm * 4 + r;
#pragma unroll
        for (int q = 0; q < 2; ++q) {
            int hidx = h0 + q * 32 + tn;
            float ig = acc[r][q * 4 + 0] + rb[0 * 256 + hidx];
            float fg = acc[r][q * 4 + 1] + rb[1 * 256 + hidx];
            float gg = acc[r][q * 4 + 2] + rb[2 * 256 + hidx];
            float og = acc[r][q * 4 + 3] + rb[3 * 256 + hidx];
            float c_old = Cst[(size_t)b * 256 + hidx];
            float c_new = sigmoidf_(fg) * c_old + sigmoidf_(ig) * tanhf(gg);
            float h_new = sigmoidf_(og) * tanhf(c_new);
            Cst[(size_t)b * 256 + hidx] = c_new;
            Hout[(size_t)b * 256 + hidx] = h_new;
        }
    }
}

// ---------------- persistent decode: steps 1..127 in one launch ----------------
// 128 blocks (16 b-tiles x 8 gate-col tiles), 1 block/SM, all co-resident.
// Block tile: 64 batch x 128 gate-cols (32 h x 4 gates). W slice cached in smem for all
// 127 steps; c lives in registers; h exchanged through L2 with a software grid barrier.
// Inner product uses packed fma.rn.f32x2 pairing even/odd k (fold at the end).
#define DP_NBLK  128
#define DP_WROWS 128           // gate-cols per block
#define DP_AROWS 64            // batch rows per block
#define DP_STRD  260           // row stride in floats: 1040B = 16B-aligned, ≡16 mod 128
#define DP_SMEM  ((DP_WROWS + DP_AROWS) * DP_STRD * 4)

__device__ __forceinline__ void grid_barrier_()
{
    __threadfence();
    __syncthreads();
    if (threadIdx.x == 0) {
        unsigned gen = *(volatile unsigned*)&g_bar_gen;
        unsigned t = atomicAdd(&g_bar_arrive, 1u);
        if (t == DP_NBLK - 1) {
            atomicExch(&g_bar_arrive, 0u);
            __threadfence();
            atomicAdd(&g_bar_gen, 1u);       // release
        } else {
            while (*(volatile unsigned*)&g_bar_gen == gen) { __nanosleep(64); }
        }
        __threadfence();
    }
    __syncthreads();
}

__global__ __launch_bounds__(256, 1)
void decode_persist_kernel(const float* __restrict__ rW,
                           const float* __restrict__ rb,
                           const float* __restrict__ cinit,
                           float* __restrict__ outs)
{
    extern __shared__ float smem[];
    float* Ws = smem;                          // [128][260]: row g*32+jj <- rW row g*256+h0+jj
    float* As = smem + DP_WROWS * DP_STRD;     // [64][260]

    const int tid = threadIdx.x;
    const int w   = tid >> 5;     // warp 0..7 -> 8 batch rows
    const int j   = tid & 31;     // lane -> h index h0+j (all 4 gates)
    const int b0  = blockIdx.x * 64;
    const int h0  = blockIdx.y * 32;

    // ---- stage W slice once ----
    for (int i = tid; i < DP_WROWS * 64; i += 256) {
        int row = i >> 6;                 // 0..127
        int k4  = (i & 63) * 4;
        int g = row >> 5, jj = row & 31;
        float4 v = *reinterpret_cast<const float4*>(&rW[(size_t)((g << 8) + h0 + jj) * 256 + k4]);
        *reinterpret_cast<float4*>(&Ws[row * DP_STRD + k4]) = v;
    }

    float rbv[4];
#pragma unroll
    for (int g = 0; g < 4; ++g) rbv[g] = rb[g * 256 + h0 + j];

    float creg[8];
#pragma unroll
    for (int r = 0; r < 8; ++r)
        creg[r] = cinit[(size_t)(b0 + w * 8 + r) * 256 + h0 + j];

    const unsigned aWs = (unsigned)__cvta_generic_to_shared(Ws) + (unsigned)(j * DP_STRD * 4);
    const unsigned aAs = (unsigned)__cvta_generic_to_shared(As) + (unsigned)(w * 8 * DP_STRD * 4);

    for (int s = 1; s < 128; ++s) {
        grid_barrier_();   // step s-1 h fully written (also covers initial W staging)

        const float* hprev = outs + (size_t)(s - 1) * NB * HH;
        for (int i = tid; i < DP_AROWS * 64; i += 256) {
            int row = i >> 6;
            int k4  = (i & 63) * 4;
            float4 v = *reinterpret_cast<const float4*>(&hprev[(size_t)(b0 + row) * 256 + k4]);
            *reinterpret_cast<float4*>(&As[row * DP_STRD + k4]) = v;
        }
        __syncthreads();

        unsigned long long acc[8][4];
#pragma unroll
        for (int r = 0; r < 8; ++r)
#pragma unroll
            for (int g = 0; g < 4; ++g) acc[r][g] = 0ull;

#pragma unroll 2
        for (int k4 = 0; k4 < 256; k4 += 4) {
            unsigned long long bg[4][2];
#pragma unroll
            for (int g = 0; g < 4; ++g)
                lds_v2u64(bg[g][0], bg[g][1], aWs + (unsigned)((g * 32 * DP_STRD + k4) * 4));
#pragma unroll
            for (int r = 0; r < 8; ++r) {
                unsigned long long a0, a1;
                lds_v2u64(a0, a1, aAs + (unsigned)((r * DP_STRD + k4) * 4));
#pragma unroll
                for (int g = 0; g < 4; ++g) {
                    ffma2(acc[r][g], a0, bg[g][0]);
                    ffma2(acc[r][g], a1, bg[g][1]);
                }
            }
        }

        float* hout = outs + (size_t)s * NB * HH;
#pragma unroll
        for (int r = 0; r < 8; ++r) {
            float gi = u64lo(acc[r][0]) + u64hi(acc[r][0]) + rbv[0];
            float gf = u64lo(acc[r][1]) + u64hi(acc[r][1]) + rbv[1];
            float gg = u64lo(acc[r][2]) + u64hi(acc[r][2]) + rbv[2];
            float go = u64lo(acc[r][3]) + u64hi(acc[r][3]) + rbv[3];
            float cn = sigmoidf_(gf) * creg[r] + sigmoidf_(gi) * tanhf(gg);
            creg[r] = cn;
            hout[(size_t)(b0 + w * 8 + r) * 256 + h0 + j] = sigmoidf_(go) * tanhf(cn);
        }
    }
}

// ---------------- predictor LSTM (whole 128-step recurrence) + epilogue ----------------
__global__ __launch_bounds__(128)
void predictor_kernel(const float* __restrict__ XW, const float* __restrict__ pWhh,
                      float* __restrict__ out)
{
    __shared__ float sWt[32 * 132];
    __shared__ float sh[4][32];
    const int tid = threadIdx.x;
    const int w = tid >> 5;
    const int j = tid & 31;
    const int b = blockIdx.x * 4 + w;

    for (int i = tid; i < 128 * 32; i += 128) {
        int row = i >> 5, k = i & 31;
        sWt[k * 132 + row] = pWhh[i];
    }
    sh[w][j] = 0.0f;
    float cp = 0.0f;
    __syncthreads();

    float nxt[4];
#pragma unroll
    for (int t = 0; t < 4; ++t) nxt[t] = XW[(size_t)b * 128 + t * 32 + j];

    for (int s = 0; s < 128; ++s) {
        float g0 = nxt[0], g1 = nxt[1], g2 = nxt[2], g3 = nxt[3];
        if (s + 1 < 128) {
#pragma unroll
            for (int t = 0; t < 4; ++t)
                nxt[t] = XW[(size_t)((s + 1) * 1024 + b) * 128 + t * 32 + j];
        }
#pragma unroll
        for (int k = 0; k < 32; ++k) {
            float hk = sh[w][k];
            const float* wr = &sWt[k * 132];
            g0 += hk * wr[j];
            g1 += hk * wr[32 + j];
            g2 += hk * wr[64 + j];
            g3 += hk * wr[96 + j];
        }
        float ig = sigmoidf_(g0);
        float fg = sigmoidf_(g1);
        float gg = tanhf(g2);
        float og = sigmoidf_(g3);
        cp = fg * cp + ig * gg;
        float hv = og * tanhf(cp);
        __syncwarp();
        sh[w][j] = hv;
        __syncwarp();

        float mv = (j < 31) ? hv : -3.0e38f;
#pragma unroll
        for (int o = 16; o > 0; o >>= 1) mv = fmaxf(mv, __shfl_xor_sync(0xffffffffu, mv, o));
        float e = (j < 31) ? expf(hv - mv) : 0.0f;
        float sum = e;
#pragma unroll
        for (int o = 16; o > 0; o >>= 1) sum += __shfl_xor_sync(0xffffffffu, sum, o);
        float ov = (j < 31) ? (e / sum) : sigmoidf_(hv);
        out[(size_t)(b * 128 + s) * 32 + j] = ov;
    }
}

// ---------------- launch ----------------
extern "C" void kernel_launch(void* const* d_in, const int* in_sizes, int n_in,
                              void* d_out, int out_size)
{
    const float* x    = (const float*)d_in[0];
    const float* W1   = (const float*)d_in[1];
    const float* b1   = (const float*)d_in[2];
    const float* W2   = (const float*)d_in[3];
    const float* b2   = (const float*)d_in[4];
    const float* W3   = (const float*)d_in[5];
    const float* b3   = (const float*)d_in[6];
    const float* Wh1  = (const float*)d_in[7];
    const float* bh1  = (const float*)d_in[8];
    const float* Wh2  = (const float*)d_in[9];
    const float* bh2  = (const float*)d_in[10];
    const float* Wc1  = (const float*)d_in[11];
    const float* bc1  = (const float*)d_in[12];
    const float* Wc2  = (const float*)d_in[13];
    const float* bc2  = (const float*)d_in[14];
    const float* Wx1  = (const float*)d_in[15];
    const float* bx1  = (const float*)d_in[16];
    const float* Wx2  = (const float*)d_in[17];
    const float* bx2  = (const float*)d_in[18];
    const float* rWih = (const float*)d_in[19];
    const float* rWhh = (const float*)d_in[20];
    const float* rbih = (const float*)d_in[21];
    const float* rbhh = (const float*)d_in[22];
    const float* pWih = (const float*)d_in[23];
    const float* pWhh = (const float*)d_in[24];
    const float* pbih = (const float*)d_in[25];
    const float* pbhh = (const float*)d_in[26];

    float *t1, *t2, *hbuf, *cbuf, *x0buf, *rW, *rb, *pb, *outs, *XW;
    cudaGetSymbolAddress((void**)&t1, g_t1);
    cudaGetSymbolAddress((void**)&t2, g_t2);
    cudaGetSymbolAddress((void**)&hbuf, g_h);
    cudaGetSymbolAddress((void**)&cbuf, g_c);
    cudaGetSymbolAddress((void**)&x0buf, g_x0);
    cudaGetSymbolAddress((void**)&rW, g_rW);
    cudaGetSymbolAddress((void**)&rb, g_rb);
    cudaGetSymbolAddress((void**)&pb, g_pb);
    cudaGetSymbolAddress((void**)&outs, g_outs);
    cudaGetSymbolAddress((void**)&XW, g_XW);

    cudaFuncSetAttribute(decode_persist_kernel,
                         cudaFuncAttributeMaxDynamicSharedMemorySize, DP_SMEM);

    // fused weight/bias sums
    prep_kernel<<<512, 512>>>(rWih, rWhh, rbih, rbhh, pbih, pbhh, rW, rb, pb);

    // MLP trunk + heads
    linear_kernel<<<dim3(16, 8), 256>>>(x,  W1,  b1,  t1, 1024, 512, 128, 1);
    linear_kernel<<<dim3(16, 8), 256>>>(t1, W2,  b2,  t2, 1024, 512, 512, 1);
    linear_kernel<<<dim3(16, 8), 256>>>(t2, W3,  b3,  t1, 1024, 512, 512, 1);
    linear_kernel<<<dim3(16, 8), 256>>>(t1, Wh1, bh1, t2, 1024, 512, 512, 1);
    linear_kernel<<<dim3(16, 4), 256>>>(t2, Wh2, bh2, hbuf, 1024, 256, 512, 0);
    linear_kernel<<<dim3(16, 8), 256>>>(t1, Wc1, bc1, t2, 1024, 512, 512, 1);
    linear_kernel<<<dim3(16, 4), 256>>>(t2, Wc2, bc2, cbuf, 1024, 256, 512, 0);
    linear_kernel<<<dim3(16, 8), 256>>>(t1, Wx1, bx1, t2, 1024, 512, 512, 1);
    linear_kernel<<<dim3(16, 4), 256>>>(t2, Wx2, bx2, x0buf, 1024, 256, 512, 0);

    // decode step 0: gates = x0 @ rWih^T + h @ rWhh^T
    decode_step_kernel<<<dim3(32, 4), 256>>>(x0buf, rWih, hbuf, rWhh, rb, cbuf, outs);

    // decode steps 1..127: persistent kernel, W in smem, c in regs, FFMA2 math
    decode_persist_kernel<<<dim3(16, 8), 256, DP_SMEM>>>(rW, rb, cbuf, outs);

    // predictor input transform, batched over all steps: XW = outs @ pWih^T + pb
    linear_kernel<<<dim3(2048, 2), 256>>>(outs, pWih, pb, XW, LL * NB, 128, 256, 0);

    // full predictor recurrence + softmax/sigmoid epilogue
    predictor_kernel<<<256, 128>>>(XW, pWhh, (float*)d_out);
}